// round 4
// baseline (speedup 1.0000x reference)
#include <cuda_runtime.h>
#include <stdint.h>
#include <math.h>

#define Kc 128
#define Df 512
#define Lf 64
#define Nn 4096

// ln(2*pi) * 512
#define CONST_TERM 940.9930580015849f

typedef unsigned long long ull;

// packed f32x2 helpers (sm_100+ PTX)
#define FMA2(acc, a, b) asm("fma.rn.f32x2 %0, %1, %2, %0;" : "+l"(acc) : "l"(a), "l"(b))
#define MUL2(d, a, b)   asm("mul.rn.f32x2 %0, %1, %2;" : "=l"(d) : "l"(a), "l"(b))
#define ADD2(d, a, b)   asm("add.rn.f32x2 %0, %1, %2;" : "=l"(d) : "l"(a), "l"(b))

__device__ __forceinline__ ull pk(float v) {
    ull r; asm("mov.b64 %0, {%1, %1};" : "=l"(r) : "f"(v)); return r;
}
__device__ __forceinline__ float2 u2f(ull u) {
    float2 f; asm("mov.b64 {%0, %1}, %2;" : "=f"(f.x), "=f"(f.y) : "l"(u)); return f;
}

// ---------------- device scratch ----------------
__device__ __align__(16) float g_W[(size_t)Kc * Df * Lf];  // [k][d][l]
__device__ __align__(16) float g_iD[Kc * Df];
__device__ __align__(16) float g_iDMU[Kc * Df];
__device__ __align__(16) float g_CI[Kc * Lf * Lf];         // Cinv[i][j]
__device__ __align__(16) float g_nkw[Kc * Lf];             // -(W^T MU)
__device__ __align__(16) float g_coef[Kc];
__device__ __align__(16) float g_PC[(size_t)Kc * Nn];      // [k][n]

// ---------------------------------------------------------------------------
// prep1: per k: iD, iDMU, Lmat = I + A^T diag(iD) A (f32x2), Cholesky, Cinv,
//        nkw, coef.  Cinv stored to gmem for prep2.
// ---------------------------------------------------------------------------
__global__ __launch_bounds__(256) void prep1_kernel(const float* __restrict__ A,
                                                    const float* __restrict__ MU,
                                                    const float* __restrict__ Dm,
                                                    const float* __restrict__ PI)
{
    __shared__ float sLM[64 * 65];
    __shared__ float sCIT[64 * 68];   // sCIT[j*68+i] = Cinv[i][j]
    __shared__ float siD[512];
    __shared__ float siMU[512];
    __shared__ float sA[16 * 64];
    __shared__ float scinv[64];
    __shared__ float sv[64];
    __shared__ float sred[256];
    __shared__ float s_c1, s_slog;

    const int k = blockIdx.x;
    const int tid = threadIdx.x;
#define LM(i, j) sLM[(i) * 65 + (j)]

    // phase 1
    float c1p = 0.f, slp = 0.f;
    for (int d = tid; d < Df; d += 256) {
        float dv = Dm[k * Df + d];
        float id = 1.f / (dv * dv);
        siD[d] = id;
        g_iD[k * Df + d] = id;
        float mu = MU[k * Df + d];
        float im = id * mu;
        siMU[d] = im;
        g_iDMU[k * Df + d] = im;
        c1p += im * mu;
        slp += logf(id);
    }
    sred[tid] = c1p; __syncthreads();
    for (int s = 128; s > 0; s >>= 1) { if (tid < s) sred[tid] += sred[tid + s]; __syncthreads(); }
    if (tid == 0) s_c1 = sred[0];
    __syncthreads();
    sred[tid] = slp; __syncthreads();
    for (int s = 128; s > 0; s >>= 1) { if (tid < s) sred[tid] += sred[tid + s]; __syncthreads(); }
    if (tid == 0) s_slog = sred[0];
    __syncthreads();

    // phase 2: Lmat via f32x2, 16-d tiles
    const int tl = (tid >> 4) << 2;
    const int tm = (tid & 15) << 2;
    ull lacc2[4][2];
#pragma unroll
    for (int i = 0; i < 4; i++) { lacc2[i][0] = 0ULL; lacc2[i][1] = 0ULL; }
    float vacc = 0.f;

    const float* Ak = A + (size_t)k * Df * Lf;
    for (int d0 = 0; d0 < Df; d0 += 16) {
        *(float4*)&sA[tid * 4] = *(const float4*)(Ak + (size_t)d0 * 64 + tid * 4);
        __syncthreads();
#pragma unroll
        for (int dd = 0; dd < 16; dd++) {
            ull idp = pk(siD[d0 + dd]);
            float4 lav = *(const float4*)&sA[dd * 64 + tl];
            ulonglong2 bb = *(const ulonglong2*)&sA[dd * 64 + tm];
            ull lb0, lb1;
            MUL2(lb0, bb.x, idp);
            MUL2(lb1, bb.y, idp);
            float la[4] = {lav.x, lav.y, lav.z, lav.w};
#pragma unroll
            for (int i = 0; i < 4; i++) {
                ull ai = pk(la[i]);
                FMA2(lacc2[i][0], ai, lb0);
                FMA2(lacc2[i][1], ai, lb1);
            }
        }
        if (tid < 64) {
#pragma unroll
            for (int dd = 0; dd < 16; dd++)
                vacc += siMU[d0 + dd] * sA[dd * 64 + tid];
        }
        __syncthreads();
    }
#pragma unroll
    for (int i = 0; i < 4; i++) {
        float2 f0 = u2f(lacc2[i][0]);
        float2 f1 = u2f(lacc2[i][1]);
        float w[4] = {f0.x, f0.y, f1.x, f1.y};
#pragma unroll
        for (int j = 0; j < 4; j++)
            LM(tl + i, tm + j) = w[j] + ((tl + i) == (tm + j) ? 1.f : 0.f);
    }
    if (tid < 64) sv[tid] = vacc;
    __syncthreads();

    // phase 3: Cholesky
    for (int j = 0; j < 64; j++) {
        if (tid >= j && tid < 64) {
            float s = LM(tid, j);
            for (int p = 0; p < j; p++) s -= LM(tid, p) * LM(j, p);
            LM(tid, j) = s;
        }
        __syncthreads();
        if (tid == 0) {
            float dv = sqrtf(LM(j, j));
            LM(j, j) = dv;
            scinv[j] = 1.f / dv;
        }
        __syncthreads();
        if (tid > j && tid < 64) LM(tid, j) *= scinv[j];
        __syncthreads();
    }
    if (tid == 0) {
        float ld = 0.f;
        for (int j = 0; j < 64; j++) ld += logf(LM(j, j));
        ld *= 2.f;
        g_coef[k] = PI[k] - 0.5f * (CONST_TERM + (ld - s_slog) + s_c1);
    }

    // phase 4: triangular inverse (thread j owns column j)
    for (int idx = tid; idx < 64 * 68; idx += 256) sCIT[idx] = 0.f;
    __syncthreads();
    if (tid < 64) {
        const int j = tid;
        for (int i = j; i < 64; i++) {
            float s = (i == j) ? 1.f : 0.f;
            for (int p = j; p < i; p++) s -= LM(i, p) * sCIT[j * 68 + p];
            sCIT[j * 68 + i] = s * scinv[i];
        }
    }
    __syncthreads();

    // nkw
    if (tid < 64) {
        float s = 0.f;
        for (int p = 0; p < 64; p++) s += sCIT[p * 68 + tid] * sv[p];
        g_nkw[k * Lf + tid] = -s;
    }
    // Cinv out: g_CI[k][i*64+j] = Cinv[i][j]
    for (int idx = tid; idx < 4096; idx += 256) {
        int i = idx >> 6, j = idx & 63;
        g_CI[k * 4096 + idx] = (j <= i) ? sCIT[j * 68 + i] : 0.f;
    }
#undef LM
}

// ---------------------------------------------------------------------------
// prep2: W chunk GEMM (f32): W[d][l] = sum_p (iD*A)[d][p] Cinv[l][p]
// grid (8 dt, 128 k)
// ---------------------------------------------------------------------------
__global__ __launch_bounds__(256) void prep2_kernel(const float* __restrict__ A)
{
    __shared__ float sB[64 * 68];    // (iD*A)[d][p]
    __shared__ float sCI[64 * 68];   // sCI[p*68 + l] = Cinv[l][p]

    const int k = blockIdx.y;
    const int dt = blockIdx.x;
    const int tid = threadIdx.x;

    {
        int lr = tid >> 2;
        int lc = (tid & 3) << 4;
        float idv = g_iD[k * Df + dt * 64 + lr];
        const float* ar = A + ((size_t)k * Df + dt * 64 + lr) * Lf + lc;
#pragma unroll
        for (int q = 0; q < 4; q++) {
            float4 av = *(const float4*)(ar + 4 * q);
            av.x *= idv; av.y *= idv; av.z *= idv; av.w *= idv;
            *(float4*)&sB[lr * 68 + lc + 4 * q] = av;
        }
    }
    for (int idx = tid; idx < 4096; idx += 256) {
        int l = idx >> 6, p = idx & 63;
        sCI[p * 68 + l] = g_CI[k * 4096 + idx];
    }
    __syncthreads();

    const int td = (tid >> 4) << 2;
    const int tcl = (tid & 15) << 2;
    float wacc[4][4];
#pragma unroll
    for (int i = 0; i < 4; i++)
#pragma unroll
        for (int j = 0; j < 4; j++) wacc[i][j] = 0.f;
    for (int p = 0; p < 64; p++) {
        float la[4];
#pragma unroll
        for (int i = 0; i < 4; i++) la[i] = sB[(td + i) * 68 + p];
        float4 lcv = *(const float4*)&sCI[p * 68 + tcl];
        float lcj[4] = {lcv.x, lcv.y, lcv.z, lcv.w};
#pragma unroll
        for (int i = 0; i < 4; i++)
#pragma unroll
            for (int j = 0; j < 4; j++) wacc[i][j] += la[i] * lcj[j];
    }
#pragma unroll
    for (int i = 0; i < 4; i++) {
        float4 wv = make_float4(wacc[i][0], wacc[i][1], wacc[i][2], wacc[i][3]);
        *(float4*)&g_W[((size_t)k * Df + dt * 64 + td + i) * Lf + tcl] = wv;
    }
}

// ---------------------------------------------------------------------------
// main: per (k, 256-n tile): t = x @ W_k via packed f32x2 FMA.
// 256 threads, 8n x 8l register tiles. Double-buffered smem, register
// prefetch (LDG for chunk c+1 issued before compute(c)). q1 computed from
// prefetch registers (thread owns row n = n0 + tid).
// ---------------------------------------------------------------------------
#define SXP 264
__global__ __launch_bounds__(256) void main_kernel(const float* __restrict__ x)
{
    __shared__ __align__(16) float sX[2][16 * SXP];
    __shared__ __align__(16) float sW[2][16 * 64];
    __shared__ float sQ1[256], sB1[256];

    const int k = blockIdx.y;
    const int n0 = blockIdx.x << 8;
    const int tid = threadIdx.x;
    const int tx = tid & 7;
    const int tx8 = tx << 3;
    const int ty8 = (tid >> 3) << 3;

    const float* xrow = x + (size_t)(n0 + tid) * Df;
    const float* wbase = g_W + (size_t)k * Df * Lf;
    const float* iDk = g_iD + k * Df;
    const float* iMk = g_iDMU + k * Df;
    const int wd = tid >> 4;             // W loader: row d
    const int wl = (tid & 15) << 2;      // W loader: col l

    ull acc2[8][4];
#pragma unroll
    for (int i = 0; i < 8; i++)
#pragma unroll
        for (int j = 0; j < 4; j++) acc2[i][j] = 0ULL;
    float a1 = 0.f, b1 = 0.f;

    float4 xp[4], wp;

#define LOADC(c) do { \
    const float* xs = xrow + (c) * 16; \
    xp[0] = *(const float4*)(xs); \
    xp[1] = *(const float4*)(xs + 4); \
    xp[2] = *(const float4*)(xs + 8); \
    xp[3] = *(const float4*)(xs + 12); \
    wp = *(const float4*)(wbase + (size_t)((c) * 16 + wd) * Lf + wl); \
} while (0)

#define Q1ACC(c) do { \
    const int d0q = (c) * 16; \
    _Pragma("unroll") \
    for (int q = 0; q < 4; q++) { \
        float4 idv = *(const float4*)(iDk + d0q + 4 * q); \
        float4 imv = *(const float4*)(iMk + d0q + 4 * q); \
        a1 += xp[q].x * xp[q].x * idv.x + xp[q].y * xp[q].y * idv.y \
            + xp[q].z * xp[q].z * idv.z + xp[q].w * xp[q].w * idv.w; \
        b1 += xp[q].x * imv.x + xp[q].y * imv.y \
            + xp[q].z * imv.z + xp[q].w * imv.w; \
    } \
} while (0)

#define STOREC(buf) do { \
    float* dx = sX[buf]; \
    _Pragma("unroll") \
    for (int q = 0; q < 4; q++) { \
        dx[(4 * q + 0) * SXP + tid] = xp[q].x; \
        dx[(4 * q + 1) * SXP + tid] = xp[q].y; \
        dx[(4 * q + 2) * SXP + tid] = xp[q].z; \
        dx[(4 * q + 3) * SXP + tid] = xp[q].w; \
    } \
    *(float4*)&sW[buf][wd * 64 + wl] = wp; \
} while (0)

    LOADC(0);
    Q1ACC(0);
    STOREC(0);
    __syncthreads();

    for (int c = 0; c < 32; c++) {
        const int buf = c & 1;
        if (c < 31) LOADC(c + 1);

        const float* bx = sX[buf];
        const float* bw = sW[buf];
#pragma unroll
        for (int dd = 0; dd < 16; dd++) {
            const float* xr = bx + dd * SXP + ty8;
            float4 xa = *(const float4*)xr;
            float4 xb = *(const float4*)(xr + 4);
            ulonglong2 wA = *(const ulonglong2*)(bw + dd * 64 + tx8);
            ulonglong2 wB = *(const ulonglong2*)(bw + dd * 64 + tx8 + 4);
            ull xd;
            xd = pk(xa.x);
            FMA2(acc2[0][0], xd, wA.x); FMA2(acc2[0][1], xd, wA.y);
            FMA2(acc2[0][2], xd, wB.x); FMA2(acc2[0][3], xd, wB.y);
            xd = pk(xa.y);
            FMA2(acc2[1][0], xd, wA.x); FMA2(acc2[1][1], xd, wA.y);
            FMA2(acc2[1][2], xd, wB.x); FMA2(acc2[1][3], xd, wB.y);
            xd = pk(xa.z);
            FMA2(acc2[2][0], xd, wA.x); FMA2(acc2[2][1], xd, wA.y);
            FMA2(acc2[2][2], xd, wB.x); FMA2(acc2[2][3], xd, wB.y);
            xd = pk(xa.w);
            FMA2(acc2[3][0], xd, wA.x); FMA2(acc2[3][1], xd, wA.y);
            FMA2(acc2[3][2], xd, wB.x); FMA2(acc2[3][3], xd, wB.y);
            xd = pk(xb.x);
            FMA2(acc2[4][0], xd, wA.x); FMA2(acc2[4][1], xd, wA.y);
            FMA2(acc2[4][2], xd, wB.x); FMA2(acc2[4][3], xd, wB.y);
            xd = pk(xb.y);
            FMA2(acc2[5][0], xd, wA.x); FMA2(acc2[5][1], xd, wA.y);
            FMA2(acc2[5][2], xd, wB.x); FMA2(acc2[5][3], xd, wB.y);
            xd = pk(xb.z);
            FMA2(acc2[6][0], xd, wA.x); FMA2(acc2[6][1], xd, wA.y);
            FMA2(acc2[6][2], xd, wB.x); FMA2(acc2[6][3], xd, wB.y);
            xd = pk(xb.w);
            FMA2(acc2[7][0], xd, wA.x); FMA2(acc2[7][1], xd, wA.y);
            FMA2(acc2[7][2], xd, wB.x); FMA2(acc2[7][3], xd, wB.y);
        }

        if (c < 31) {
            Q1ACC(c + 1);
            STOREC(buf ^ 1);
        }
        __syncthreads();
    }

    sQ1[tid] = a1;
    sB1[tid] = b1;
    __syncthreads();

    // epilogue: q2 partials + combine
    ulonglong2 nk0 = *(const ulonglong2*)&g_nkw[k * Lf + tx8];
    ulonglong2 nk1 = *(const ulonglong2*)&g_nkw[k * Lf + tx8 + 4];
    ull nkw[4] = {nk0.x, nk0.y, nk1.x, nk1.y};

    float r[8];
#pragma unroll
    for (int i = 0; i < 8; i++) {
        ull s2 = 0ULL;
#pragma unroll
        for (int j = 0; j < 4; j++) {
            ull d2;
            ADD2(d2, acc2[i][j], nkw[j]);
            FMA2(s2, d2, d2);
        }
        float2 f = u2f(s2);
        r[i] = -(f.x + f.y);               // -q2 partial (this thread's 8 l's)
    }
#pragma unroll
    for (int i = 0; i < 8; i++) {
#pragma unroll
        for (int o = 1; o < 8; o <<= 1)
            r[i] += __shfl_xor_sync(0xffffffffu, r[i], o);
    }
    if (tx == 0) {
        float coef = g_coef[k];
#pragma unroll
        for (int i = 0; i < 8; i++) {
            float rr = r[i] + sQ1[ty8 + i] - 2.f * sB1[ty8 + i];
            g_PC[(size_t)k * Nn + n0 + ty8 + i] = coef - 0.5f * rr;
        }
    }
}

// ---------------------------------------------------------------------------
// lse: per n, logsumexp over k (g_PC is [k][n] -> coalesced column reads)
// ---------------------------------------------------------------------------
__global__ __launch_bounds__(256) void lse_kernel(float* __restrict__ out)
{
    const int n = blockIdx.x * 256 + threadIdx.x;
    float mx = -1e30f;
#pragma unroll 8
    for (int k = 0; k < Kc; k++) mx = fmaxf(mx, g_PC[(size_t)k * Nn + n]);
    float s = 0.f;
#pragma unroll 8
    for (int k = 0; k < Kc; k++) s += expf(g_PC[(size_t)k * Nn + n] - mx);
    out[n] = mx + logf(s);
}

extern "C" void kernel_launch(void* const* d_in, const int* in_sizes, int n_in,
                              void* d_out, int out_size)
{
    const float* x  = (const float*)d_in[0];
    const float* MU = (const float*)d_in[1];
    const float* A  = (const float*)d_in[2];
    const float* Dm = (const float*)d_in[3];
    const float* PI = (const float*)d_in[4];
    float* out = (float*)d_out;

    prep1_kernel<<<Kc, 256>>>(A, MU, Dm, PI);
    prep2_kernel<<<dim3(8, Kc), 256>>>(A);
    main_kernel<<<dim3(Nn / 256, Kc), 256>>>(x);
    lse_kernel<<<Nn / 256, 256>>>(out);
}

// round 5
// speedup vs baseline: 1.0779x; 1.0779x over previous
#include <cuda_runtime.h>
#include <stdint.h>
#include <math.h>

#define Kc 128
#define Df 512
#define Lf 64
#define Nn 4096

// ln(2*pi) * 512
#define CONST_TERM 940.9930580015849f

typedef unsigned long long ull;

// packed f32x2 helpers (sm_100+ PTX)
#define FMA2(acc, a, b) asm("fma.rn.f32x2 %0, %1, %2, %0;" : "+l"(acc) : "l"(a), "l"(b))
#define MUL2(d, a, b)   asm("mul.rn.f32x2 %0, %1, %2;" : "=l"(d) : "l"(a), "l"(b))
#define ADD2(d, a, b)   asm("add.rn.f32x2 %0, %1, %2;" : "=l"(d) : "l"(a), "l"(b))

__device__ __forceinline__ ull pk(float v) {
    ull r; asm("mov.b64 %0, {%1, %1};" : "=l"(r) : "f"(v)); return r;
}
__device__ __forceinline__ float2 u2f(ull u) {
    float2 f; asm("mov.b64 {%0, %1}, %2;" : "=f"(f.x), "=f"(f.y) : "l"(u)); return f;
}
__device__ __forceinline__ uint32_t smem_u32(const void* p) {
    uint32_t a;
    asm("{ .reg .u64 t; cvta.to.shared.u64 t, %1; cvt.u32.u64 %0, t; }" : "=r"(a) : "l"(p));
    return a;
}

// ---------------- device scratch ----------------
__device__ __align__(16) float g_W[(size_t)Kc * Df * Lf];  // [k][d][l]
__device__ __align__(16) float g_iD[Kc * Df];
__device__ __align__(16) float g_iDT[Df * Kc];             // [d][k]
__device__ __align__(16) float g_m2iMT[Df * Kc];           // [d][k] = -2*iD*MU
__device__ __align__(16) float g_CI[Kc * Lf * Lf];         // Cinv[i][j]
__device__ __align__(16) float g_nkw[Kc * Lf];             // -(W^T MU)
__device__ __align__(16) float g_coef[Kc];
__device__ __align__(16) float g_Q1[(size_t)Kc * Nn];      // q1 = x^2 iD - 2 x iDMU
__device__ __align__(16) float g_PC[(size_t)Kc * Nn];      // per-comp log dens [k][n]

// ---------------------------------------------------------------------------
// prep1: per k: iD, iDMU (+transposed copies), Lmat = I + A^T diag(iD) A
// (f32x2), Cholesky, Cinv, nkw, coef.
// ---------------------------------------------------------------------------
__global__ __launch_bounds__(256) void prep1_kernel(const float* __restrict__ A,
                                                    const float* __restrict__ MU,
                                                    const float* __restrict__ Dm,
                                                    const float* __restrict__ PI)
{
    __shared__ float sLM[64 * 65];
    __shared__ float sCIT[64 * 68];   // sCIT[j*68+i] = Cinv[i][j]
    __shared__ float siD[512];
    __shared__ float siMU[512];
    __shared__ float sA[16 * 64];
    __shared__ float scinv[64];
    __shared__ float sv[64];
    __shared__ float sred[256];
    __shared__ float s_c1, s_slog;

    const int k = blockIdx.x;
    const int tid = threadIdx.x;
#define LM(i, j) sLM[(i) * 65 + (j)]

    // phase 1
    float c1p = 0.f, slp = 0.f;
    for (int d = tid; d < Df; d += 256) {
        float dv = Dm[k * Df + d];
        float id = 1.f / (dv * dv);
        siD[d] = id;
        g_iD[k * Df + d] = id;
        g_iDT[d * Kc + k] = id;
        float mu = MU[k * Df + d];
        float im = id * mu;
        siMU[d] = im;
        g_m2iMT[d * Kc + k] = -2.f * im;
        c1p += im * mu;
        slp += logf(id);
    }
    sred[tid] = c1p; __syncthreads();
    for (int s = 128; s > 0; s >>= 1) { if (tid < s) sred[tid] += sred[tid + s]; __syncthreads(); }
    if (tid == 0) s_c1 = sred[0];
    __syncthreads();
    sred[tid] = slp; __syncthreads();
    for (int s = 128; s > 0; s >>= 1) { if (tid < s) sred[tid] += sred[tid + s]; __syncthreads(); }
    if (tid == 0) s_slog = sred[0];
    __syncthreads();

    // phase 2: Lmat via f32x2, 16-d tiles
    const int tl = (tid >> 4) << 2;
    const int tm = (tid & 15) << 2;
    ull lacc2[4][2];
#pragma unroll
    for (int i = 0; i < 4; i++) { lacc2[i][0] = 0ULL; lacc2[i][1] = 0ULL; }
    float vacc = 0.f;

    const float* Ak = A + (size_t)k * Df * Lf;
    for (int d0 = 0; d0 < Df; d0 += 16) {
        *(float4*)&sA[tid * 4] = *(const float4*)(Ak + (size_t)d0 * 64 + tid * 4);
        __syncthreads();
#pragma unroll
        for (int dd = 0; dd < 16; dd++) {
            ull idp = pk(siD[d0 + dd]);
            float4 lav = *(const float4*)&sA[dd * 64 + tl];
            ulonglong2 bb = *(const ulonglong2*)&sA[dd * 64 + tm];
            ull lb0, lb1;
            MUL2(lb0, bb.x, idp);
            MUL2(lb1, bb.y, idp);
            float la[4] = {lav.x, lav.y, lav.z, lav.w};
#pragma unroll
            for (int i = 0; i < 4; i++) {
                ull ai = pk(la[i]);
                FMA2(lacc2[i][0], ai, lb0);
                FMA2(lacc2[i][1], ai, lb1);
            }
        }
        if (tid < 64) {
#pragma unroll
            for (int dd = 0; dd < 16; dd++)
                vacc += siMU[d0 + dd] * sA[dd * 64 + tid];
        }
        __syncthreads();
    }
#pragma unroll
    for (int i = 0; i < 4; i++) {
        float2 f0 = u2f(lacc2[i][0]);
        float2 f1 = u2f(lacc2[i][1]);
        float w[4] = {f0.x, f0.y, f1.x, f1.y};
#pragma unroll
        for (int j = 0; j < 4; j++)
            LM(tl + i, tm + j) = w[j] + ((tl + i) == (tm + j) ? 1.f : 0.f);
    }
    if (tid < 64) sv[tid] = vacc;
    __syncthreads();

    // phase 3: Cholesky
    for (int j = 0; j < 64; j++) {
        if (tid >= j && tid < 64) {
            float s = LM(tid, j);
            for (int p = 0; p < j; p++) s -= LM(tid, p) * LM(j, p);
            LM(tid, j) = s;
        }
        __syncthreads();
        if (tid == 0) {
            float dv = sqrtf(LM(j, j));
            LM(j, j) = dv;
            scinv[j] = 1.f / dv;
        }
        __syncthreads();
        if (tid > j && tid < 64) LM(tid, j) *= scinv[j];
        __syncthreads();
    }
    if (tid == 0) {
        float ld = 0.f;
        for (int j = 0; j < 64; j++) ld += logf(LM(j, j));
        ld *= 2.f;
        g_coef[k] = PI[k] - 0.5f * (CONST_TERM + (ld - s_slog) + s_c1);
    }

    // phase 4: triangular inverse (thread j owns column j)
    for (int idx = tid; idx < 64 * 68; idx += 256) sCIT[idx] = 0.f;
    __syncthreads();
    if (tid < 64) {
        const int j = tid;
        for (int i = j; i < 64; i++) {
            float s = (i == j) ? 1.f : 0.f;
            for (int p = j; p < i; p++) s -= LM(i, p) * sCIT[j * 68 + p];
            sCIT[j * 68 + i] = s * scinv[i];
        }
    }
    __syncthreads();

    // nkw
    if (tid < 64) {
        float s = 0.f;
        for (int p = 0; p < 64; p++) s += sCIT[p * 68 + tid] * sv[p];
        g_nkw[k * Lf + tid] = -s;
    }
    // Cinv out
    for (int idx = tid; idx < 4096; idx += 256) {
        int i = idx >> 6, j = idx & 63;
        g_CI[k * 4096 + idx] = (j <= i) ? sCIT[j * 68 + i] : 0.f;
    }
#undef LM
}

// ---------------------------------------------------------------------------
// prep2: W chunk GEMM: W[d][l] = sum_p (iD*A)[d][p] Cinv[l][p]; grid (8, 128)
// ---------------------------------------------------------------------------
__global__ __launch_bounds__(256) void prep2_kernel(const float* __restrict__ A)
{
    __shared__ float sB[64 * 68];
    __shared__ float sCI[64 * 68];   // sCI[p*68 + l] = Cinv[l][p]

    const int k = blockIdx.y;
    const int dt = blockIdx.x;
    const int tid = threadIdx.x;

    {
        int lr = tid >> 2;
        int lc = (tid & 3) << 4;
        float idv = g_iD[k * Df + dt * 64 + lr];
        const float* ar = A + ((size_t)k * Df + dt * 64 + lr) * Lf + lc;
#pragma unroll
        for (int q = 0; q < 4; q++) {
            float4 av = *(const float4*)(ar + 4 * q);
            av.x *= idv; av.y *= idv; av.z *= idv; av.w *= idv;
            *(float4*)&sB[lr * 68 + lc + 4 * q] = av;
        }
    }
    for (int idx = tid; idx < 4096; idx += 256) {
        int l = idx >> 6, p = idx & 63;
        sCI[p * 68 + l] = g_CI[k * 4096 + idx];
    }
    __syncthreads();

    const int td = (tid >> 4) << 2;
    const int tcl = (tid & 15) << 2;
    float wacc[4][4];
#pragma unroll
    for (int i = 0; i < 4; i++)
#pragma unroll
        for (int j = 0; j < 4; j++) wacc[i][j] = 0.f;
    for (int p = 0; p < 64; p++) {
        float la[4];
#pragma unroll
        for (int i = 0; i < 4; i++) la[i] = sB[(td + i) * 68 + p];
        float4 lcv = *(const float4*)&sCI[p * 68 + tcl];
        float lcj[4] = {lcv.x, lcv.y, lcv.z, lcv.w};
#pragma unroll
        for (int i = 0; i < 4; i++)
#pragma unroll
            for (int j = 0; j < 4; j++) wacc[i][j] += la[i] * lcj[j];
    }
#pragma unroll
    for (int i = 0; i < 4; i++) {
        float4 wv = make_float4(wacc[i][0], wacc[i][1], wacc[i][2], wacc[i][3]);
        *(float4*)&g_W[((size_t)k * Df + dt * 64 + td + i) * Lf + tcl] = wv;
    }
}

// ---------------------------------------------------------------------------
// q1: g_Q1[k][n] = sum_d x^2 iD - 2 x iDMU.  grid (64 ntile, 2 ktile), 256 thr
// ---------------------------------------------------------------------------
__global__ __launch_bounds__(256) void q1_kernel(const float* __restrict__ x)
{
    __shared__ __align__(16) float sxt[64 * 20];
    __shared__ __align__(16) float sx2[64 * 20];
    __shared__ __align__(16) float sid[16 * 68];
    __shared__ __align__(16) float sim[16 * 68];

    const int n0 = blockIdx.x << 6;
    const int k0 = blockIdx.y << 6;
    const int tid = threadIdx.x;
    const int tn = (tid >> 4) << 2;
    const int tk = (tid & 15) << 2;
    const int xr = tid >> 2, xc = (tid & 3) << 2;
    const int ir = tid >> 4, ic = (tid & 15) << 2;

    ull acc2[4][2];
#pragma unroll
    for (int i = 0; i < 4; i++) { acc2[i][0] = 0ULL; acc2[i][1] = 0ULL; }

    for (int c = 0; c < 32; c++) {
        float4 v = *(const float4*)(x + (size_t)(n0 + xr) * Df + c * 16 + xc);
        *(float4*)&sxt[xr * 20 + xc] = v;
        float4 v2 = make_float4(v.x * v.x, v.y * v.y, v.z * v.z, v.w * v.w);
        *(float4*)&sx2[xr * 20 + xc] = v2;
        *(float4*)&sid[ir * 68 + ic] = *(const float4*)&g_iDT[(size_t)(c * 16 + ir) * Kc + k0 + ic];
        *(float4*)&sim[ir * 68 + ic] = *(const float4*)&g_m2iMT[(size_t)(c * 16 + ir) * Kc + k0 + ic];
        __syncthreads();
#pragma unroll
        for (int dd = 0; dd < 16; dd++) {
            ulonglong2 idp = *(const ulonglong2*)&sid[dd * 68 + tk];
            ulonglong2 imp = *(const ulonglong2*)&sim[dd * 68 + tk];
#pragma unroll
            for (int i = 0; i < 4; i++) {
                float xv = sxt[(tn + i) * 20 + dd];
                float x2 = sx2[(tn + i) * 20 + dd];
                ull xp = pk(xv), x2p = pk(x2);
                FMA2(acc2[i][0], x2p, idp.x);
                FMA2(acc2[i][1], x2p, idp.y);
                FMA2(acc2[i][0], xp, imp.x);
                FMA2(acc2[i][1], xp, imp.y);
            }
        }
        __syncthreads();
    }
#pragma unroll
    for (int i = 0; i < 4; i++)
#pragma unroll
        for (int j = 0; j < 2; j++) {
            float2 f = u2f(acc2[i][j]);
            g_Q1[(size_t)(k0 + tk + 2 * j) * Nn + n0 + tn + i] = f.x;
            g_Q1[(size_t)(k0 + tk + 2 * j + 1) * Nn + n0 + tn + i] = f.y;
        }
}

// ---------------------------------------------------------------------------
// main: pure GEMM t = x @ W_k (f32x2) + q2 epilogue.
// 128 threads, 128n x 64l per CTA, cp.async 3-stage pipeline.
// Thread (ty=tid>>3, tx=tid&7): rows ty+16i (i=0..7), l-cols tx*8..tx*8+7.
// ---------------------------------------------------------------------------
#define XST 20
__global__ __launch_bounds__(128) void main_kernel(const float* __restrict__ x)
{
    __shared__ __align__(16) float sX[3][128 * XST];
    __shared__ __align__(16) float sW[3][16 * 64];

    const int k = blockIdx.y;
    const int n0 = blockIdx.x << 7;
    const int tid = threadIdx.x;
    const int tx = tid & 7, tx8 = tx << 3;
    const int ty = tid >> 3;

    const float* xrow = x + (size_t)(n0 + tid) * Df;
    const float* wbase = g_W + (size_t)k * Df * Lf;

#define ISSUE(c, s) do { \
    uint32_t xs = smem_u32(&sX[s][tid * XST]); \
    const float* gx = xrow + (c) * 16; \
    asm volatile("cp.async.ca.shared.global [%0], [%1], 16;" :: "r"(xs), "l"(gx) : "memory"); \
    asm volatile("cp.async.ca.shared.global [%0], [%1], 16;" :: "r"(xs + 16), "l"(gx + 4) : "memory"); \
    asm volatile("cp.async.ca.shared.global [%0], [%1], 16;" :: "r"(xs + 32), "l"(gx + 8) : "memory"); \
    asm volatile("cp.async.ca.shared.global [%0], [%1], 16;" :: "r"(xs + 48), "l"(gx + 12) : "memory"); \
    uint32_t ws = smem_u32(&sW[s][tid * 4]); \
    const float* gw = wbase + (size_t)(c) * 1024 + tid * 4; \
    asm volatile("cp.async.ca.shared.global [%0], [%1], 16;" :: "r"(ws), "l"(gw) : "memory"); \
    asm volatile("cp.async.ca.shared.global [%0], [%1], 16;" :: "r"(ws + 2048), "l"(gw + 512) : "memory"); \
    asm volatile("cp.async.commit_group;" ::: "memory"); \
} while (0)

    ull acc2[8][4];
#pragma unroll
    for (int i = 0; i < 8; i++)
#pragma unroll
        for (int j = 0; j < 4; j++) acc2[i][j] = 0ULL;

    ISSUE(0, 0);
    ISSUE(1, 1);

    int stage = 0;
    for (int c = 0; c < 32; c++) {
        if (c + 2 < 32) {
            int s2 = stage + 2; if (s2 >= 3) s2 -= 3;
            ISSUE(c + 2, s2);
            asm volatile("cp.async.wait_group 2;" ::: "memory");
        } else {
            asm volatile("cp.async.wait_group 0;" ::: "memory");
        }
        __syncthreads();

        const float* bx = sX[stage];
        const float* bw = sW[stage];
#pragma unroll
        for (int g = 0; g < 4; g++) {
            float4 xq[8];
#pragma unroll
            for (int i = 0; i < 8; i++)
                xq[i] = *(const float4*)&bx[(ty + 16 * i) * XST + g * 4];
#pragma unroll
            for (int d2 = 0; d2 < 4; d2++) {
                const int dd = g * 4 + d2;
                ulonglong2 wA = *(const ulonglong2*)&bw[dd * 64 + tx8];
                ulonglong2 wB = *(const ulonglong2*)&bw[dd * 64 + tx8 + 4];
#pragma unroll
                for (int i = 0; i < 8; i++) {
                    float xv = (d2 == 0) ? xq[i].x : (d2 == 1) ? xq[i].y
                             : (d2 == 2) ? xq[i].z : xq[i].w;
                    ull xd = pk(xv);
                    FMA2(acc2[i][0], xd, wA.x);
                    FMA2(acc2[i][1], xd, wA.y);
                    FMA2(acc2[i][2], xd, wB.x);
                    FMA2(acc2[i][3], xd, wB.y);
                }
            }
        }
        __syncthreads();
        stage++; if (stage == 3) stage = 0;
    }

    // epilogue: q2 partials over this thread's 8 l's, reduce over tx
    ulonglong2 nk0 = *(const ulonglong2*)&g_nkw[k * Lf + tx8];
    ulonglong2 nk1 = *(const ulonglong2*)&g_nkw[k * Lf + tx8 + 4];
    ull nkw[4] = {nk0.x, nk0.y, nk1.x, nk1.y};

    float r[8];
#pragma unroll
    for (int i = 0; i < 8; i++) {
        ull s2 = 0ULL;
#pragma unroll
        for (int j = 0; j < 4; j++) {
            ull d2;
            ADD2(d2, acc2[i][j], nkw[j]);
            FMA2(s2, d2, d2);
        }
        float2 f = u2f(s2);
        r[i] = -(f.x + f.y);           // -q2 partial
    }
#pragma unroll
    for (int i = 0; i < 8; i++) {
#pragma unroll
        for (int o = 1; o < 8; o <<= 1)
            r[i] += __shfl_xor_sync(0xffffffffu, r[i], o);
    }
    if (tx == 0) {
        float coef = g_coef[k];
#pragma unroll
        for (int i = 0; i < 8; i++) {
            int n = n0 + ty + 16 * i;
            float q1c = g_Q1[(size_t)k * Nn + n];
            g_PC[(size_t)k * Nn + n] = coef - 0.5f * (q1c + r[i]);
        }
    }
#undef ISSUE
}

// ---------------------------------------------------------------------------
// lse: 4 threads per n, logsumexp over k.  grid 64, block 256.
// ---------------------------------------------------------------------------
__global__ __launch_bounds__(256) void lse_kernel(float* __restrict__ out)
{
    const int tid = threadIdx.x;
    const int q = tid & 3;
    const int n = blockIdx.x * 64 + (tid >> 2);
    const float* pc = g_PC + n + (size_t)q * 32 * Nn;

    float v[32];
#pragma unroll
    for (int j = 0; j < 32; j++) v[j] = pc[(size_t)j * Nn];
    float mx = v[0];
#pragma unroll
    for (int j = 1; j < 32; j++) mx = fmaxf(mx, v[j]);
    mx = fmaxf(mx, __shfl_xor_sync(0xffffffffu, mx, 1));
    mx = fmaxf(mx, __shfl_xor_sync(0xffffffffu, mx, 2));
    float s = 0.f;
#pragma unroll
    for (int j = 0; j < 32; j++) s += expf(v[j] - mx);
    s += __shfl_xor_sync(0xffffffffu, s, 1);
    s += __shfl_xor_sync(0xffffffffu, s, 2);
    if (q == 0) out[n] = mx + logf(s);
}

extern "C" void kernel_launch(void* const* d_in, const int* in_sizes, int n_in,
                              void* d_out, int out_size)
{
    const float* x  = (const float*)d_in[0];
    const float* MU = (const float*)d_in[1];
    const float* A  = (const float*)d_in[2];
    const float* Dm = (const float*)d_in[3];
    const float* PI = (const float*)d_in[4];
    float* out = (float*)d_out;

    prep1_kernel<<<Kc, 256>>>(A, MU, Dm, PI);
    prep2_kernel<<<dim3(8, Kc), 256>>>(A);
    q1_kernel<<<dim3(Nn / 64, Kc / 64), 256>>>(x);
    main_kernel<<<dim3(Nn / 128, Kc), 128>>>(x);
    lse_kernel<<<Nn / 64, 256>>>(out);
}

// round 6
// speedup vs baseline: 2.8840x; 2.6756x over previous
#include <cuda_runtime.h>
#include <cuda_bf16.h>
#include <stdint.h>
#include <math.h>

#define Kc 128
#define Df 512
#define Lf 64
#define Nn 4096

// ln(2*pi) * 512
#define CONST_TERM 940.9930580015849f

typedef unsigned long long ull;

// packed f32x2 helpers (sm_100+ PTX)
#define FMA2(acc, a, b) asm("fma.rn.f32x2 %0, %1, %2, %0;" : "+l"(acc) : "l"(a), "l"(b))
#define MUL2(d, a, b)   asm("mul.rn.f32x2 %0, %1, %2;" : "=l"(d) : "l"(a), "l"(b))

__device__ __forceinline__ ull pk(float v) {
    ull r; asm("mov.b64 %0, {%1, %1};" : "=l"(r) : "f"(v)); return r;
}
__device__ __forceinline__ float2 u2f(ull u) {
    float2 f; asm("mov.b64 {%0, %1}, %2;" : "=f"(f.x), "=f"(f.y) : "l"(u)); return f;
}
__device__ __forceinline__ uint32_t smem_u32(const void* p) {
    uint32_t a;
    asm("{ .reg .u64 t; cvta.to.shared.u64 t, %1; cvt.u32.u64 %0, t; }" : "=r"(a) : "l"(p));
    return a;
}

// bf16 hi/lo split pack: returns hi bf16x2, writes lo bf16x2
__device__ __forceinline__ uint32_t bfsplit(float2 e, uint32_t& lo) {
    __nv_bfloat16 h0 = __float2bfloat16(e.x);
    __nv_bfloat16 h1 = __float2bfloat16(e.y);
    __nv_bfloat16 l0 = __float2bfloat16(e.x - __bfloat162float(h0));
    __nv_bfloat16 l1 = __float2bfloat16(e.y - __bfloat162float(h1));
    __nv_bfloat162 hp, lp;
    hp.x = h0; hp.y = h1; lp.x = l0; lp.y = l1;
    lo = *(uint32_t*)&lp;
    return *(uint32_t*)&hp;
}

// mma.sync m16n8k16 bf16 (A row, B col, f32 accum)
#define MMA(d, a, b0, b1) \
    asm volatile("mma.sync.aligned.m16n8k16.row.col.f32.bf16.bf16.f32 " \
        "{%0,%1,%2,%3}, {%4,%5,%6,%7}, {%8,%9}, {%0,%1,%2,%3};" \
        : "+f"((d)[0]), "+f"((d)[1]), "+f"((d)[2]), "+f"((d)[3]) \
        : "r"((a).x), "r"((a).y), "r"((a).z), "r"((a).w), "r"(b0), "r"(b1))

#define CP16(dst_u32, src_ptr) \
    asm volatile("cp.async.ca.shared.global [%0], [%1], 16;" :: "r"(dst_u32), "l"(src_ptr) : "memory")

// ---------------- device scratch ----------------
__device__ __align__(16) float g_W[(size_t)Kc * Df * Lf];  // [k][d][l]
__device__ __align__(16) float g_iD[Kc * Df];
__device__ __align__(16) float g_iDT[Df * Kc];             // [d][k]
__device__ __align__(16) float g_m2iMT[Df * Kc];           // [d][k] = -2*iD*MU
__device__ __align__(16) float g_CI[Kc * Lf * Lf];         // Cinv[i][j]
__device__ __align__(16) float g_nkw[Kc * Lf];             // -(W^T MU)
__device__ __align__(16) float g_coef[Kc];
__device__ __align__(16) float g_Q1[(size_t)Kc * Nn];      // q1 = x^2 iD - 2 x iDMU
__device__ __align__(16) float g_PC[(size_t)Kc * Nn];      // per-comp log dens [k][n]
// mma fragments: x A-frags [dchunk 32][ntile 256][hi/lo][lane 32] uint4
__device__ __align__(16) uint4 g_xf[32 * 256 * 2 * 32];
// W B-frags [k 128][dchunk 32][ltile 8][lane 32] uint4 {bhi0,bhi1,blo0,blo1}
__device__ __align__(16) uint4 g_wf[(size_t)Kc * 32 * 8 * 32];

// ---------------------------------------------------------------------------
// xcvt: build x A-fragments (bf16 hi/lo) in mma m16n8k16 layout
// ---------------------------------------------------------------------------
__global__ __launch_bounds__(256) void xcvt_kernel(const float* __restrict__ x)
{
    int idx = blockIdx.x * 256 + threadIdx.x;       // 262144 total
    int lane = idx & 31, nt = (idx >> 5) & 255, dc = idx >> 13;
    int g = lane >> 2, tg = lane & 3;
    const float* xr0 = x + (size_t)(nt * 16 + g) * Df + dc * 16 + tg * 2;
    float2 e00 = *(const float2*)xr0;               // row g,   k 2tg..2tg+1
    float2 e10 = *(const float2*)(xr0 + 8 * Df);    // row g+8
    float2 e01 = *(const float2*)(xr0 + 8);         // row g,   k +8
    float2 e11 = *(const float2*)(xr0 + 8 * Df + 8);
    uint4 hv, lv;
    hv.x = bfsplit(e00, lv.x);
    hv.y = bfsplit(e10, lv.y);
    hv.z = bfsplit(e01, lv.z);
    hv.w = bfsplit(e11, lv.w);
    size_t o = ((size_t)(dc * 256 + nt) * 2) * 32 + lane;
    g_xf[o] = hv;
    g_xf[o + 32] = lv;
}

// ---------------------------------------------------------------------------
// prep1: per k: iD, iDMU (+transposed), Lmat = I + A^T diag(iD) A (f32x2),
// Cholesky, Cinv, nkw, coef.
// ---------------------------------------------------------------------------
__global__ __launch_bounds__(256) void prep1_kernel(const float* __restrict__ A,
                                                    const float* __restrict__ MU,
                                                    const float* __restrict__ Dm,
                                                    const float* __restrict__ PI)
{
    __shared__ float sLM[64 * 65];
    __shared__ float sCIT[64 * 68];   // sCIT[j*68+i] = Cinv[i][j]
    __shared__ float siD[512];
    __shared__ float siMU[512];
    __shared__ float sA[16 * 64];
    __shared__ float scinv[64];
    __shared__ float sv[64];
    __shared__ float sred[256];
    __shared__ float s_c1, s_slog;

    const int k = blockIdx.x;
    const int tid = threadIdx.x;
#define LM(i, j) sLM[(i) * 65 + (j)]

    float c1p = 0.f, slp = 0.f;
    for (int d = tid; d < Df; d += 256) {
        float dv = Dm[k * Df + d];
        float id = 1.f / (dv * dv);
        siD[d] = id;
        g_iD[k * Df + d] = id;
        g_iDT[d * Kc + k] = id;
        float mu = MU[k * Df + d];
        float im = id * mu;
        siMU[d] = im;
        g_m2iMT[d * Kc + k] = -2.f * im;
        c1p += im * mu;
        slp += logf(id);
    }
    sred[tid] = c1p; __syncthreads();
    for (int s = 128; s > 0; s >>= 1) { if (tid < s) sred[tid] += sred[tid + s]; __syncthreads(); }
    if (tid == 0) s_c1 = sred[0];
    __syncthreads();
    sred[tid] = slp; __syncthreads();
    for (int s = 128; s > 0; s >>= 1) { if (tid < s) sred[tid] += sred[tid + s]; __syncthreads(); }
    if (tid == 0) s_slog = sred[0];
    __syncthreads();

    const int tl = (tid >> 4) << 2;
    const int tm = (tid & 15) << 2;
    ull lacc2[4][2];
#pragma unroll
    for (int i = 0; i < 4; i++) { lacc2[i][0] = 0ULL; lacc2[i][1] = 0ULL; }
    float vacc = 0.f;

    const float* Ak = A + (size_t)k * Df * Lf;
    for (int d0 = 0; d0 < Df; d0 += 16) {
        *(float4*)&sA[tid * 4] = *(const float4*)(Ak + (size_t)d0 * 64 + tid * 4);
        __syncthreads();
#pragma unroll
        for (int dd = 0; dd < 16; dd++) {
            ull idp = pk(siD[d0 + dd]);
            float4 lav = *(const float4*)&sA[dd * 64 + tl];
            ulonglong2 bb = *(const ulonglong2*)&sA[dd * 64 + tm];
            ull lb0, lb1;
            MUL2(lb0, bb.x, idp);
            MUL2(lb1, bb.y, idp);
            float la[4] = {lav.x, lav.y, lav.z, lav.w};
#pragma unroll
            for (int i = 0; i < 4; i++) {
                ull ai = pk(la[i]);
                FMA2(lacc2[i][0], ai, lb0);
                FMA2(lacc2[i][1], ai, lb1);
            }
        }
        if (tid < 64) {
#pragma unroll
            for (int dd = 0; dd < 16; dd++)
                vacc += siMU[d0 + dd] * sA[dd * 64 + tid];
        }
        __syncthreads();
    }
#pragma unroll
    for (int i = 0; i < 4; i++) {
        float2 f0 = u2f(lacc2[i][0]);
        float2 f1 = u2f(lacc2[i][1]);
        float w[4] = {f0.x, f0.y, f1.x, f1.y};
#pragma unroll
        for (int j = 0; j < 4; j++)
            LM(tl + i, tm + j) = w[j] + ((tl + i) == (tm + j) ? 1.f : 0.f);
    }
    if (tid < 64) sv[tid] = vacc;
    __syncthreads();

    for (int j = 0; j < 64; j++) {
        if (tid >= j && tid < 64) {
            float s = LM(tid, j);
            for (int p = 0; p < j; p++) s -= LM(tid, p) * LM(j, p);
            LM(tid, j) = s;
        }
        __syncthreads();
        if (tid == 0) {
            float dv = sqrtf(LM(j, j));
            LM(j, j) = dv;
            scinv[j] = 1.f / dv;
        }
        __syncthreads();
        if (tid > j && tid < 64) LM(tid, j) *= scinv[j];
        __syncthreads();
    }
    if (tid == 0) {
        float ld = 0.f;
        for (int j = 0; j < 64; j++) ld += logf(LM(j, j));
        ld *= 2.f;
        g_coef[k] = PI[k] - 0.5f * (CONST_TERM + (ld - s_slog) + s_c1);
    }

    for (int idx = tid; idx < 64 * 68; idx += 256) sCIT[idx] = 0.f;
    __syncthreads();
    if (tid < 64) {
        const int j = tid;
        for (int i = j; i < 64; i++) {
            float s = (i == j) ? 1.f : 0.f;
            for (int p = j; p < i; p++) s -= LM(i, p) * sCIT[j * 68 + p];
            sCIT[j * 68 + i] = s * scinv[i];
        }
    }
    __syncthreads();

    if (tid < 64) {
        float s = 0.f;
        for (int p = 0; p < 64; p++) s += sCIT[p * 68 + tid] * sv[p];
        g_nkw[k * Lf + tid] = -s;
    }
    for (int idx = tid; idx < 4096; idx += 256) {
        int i = idx >> 6, j = idx & 63;
        g_CI[k * 4096 + idx] = (j <= i) ? sCIT[j * 68 + i] : 0.f;
    }
#undef LM
}

// ---------------------------------------------------------------------------
// prep2: W chunk GEMM: W[d][l] = sum_p (iD*A)[d][p] Cinv[l][p]; grid (8, 128)
// ---------------------------------------------------------------------------
__global__ __launch_bounds__(256) void prep2_kernel(const float* __restrict__ A)
{
    __shared__ float sB[64 * 68];
    __shared__ float sCI[64 * 68];   // sCI[p*68 + l] = Cinv[l][p]

    const int k = blockIdx.y;
    const int dt = blockIdx.x;
    const int tid = threadIdx.x;

    {
        int lr = tid >> 2;
        int lc = (tid & 3) << 4;
        float idv = g_iD[k * Df + dt * 64 + lr];
        const float* ar = A + ((size_t)k * Df + dt * 64 + lr) * Lf + lc;
#pragma unroll
        for (int q = 0; q < 4; q++) {
            float4 av = *(const float4*)(ar + 4 * q);
            av.x *= idv; av.y *= idv; av.z *= idv; av.w *= idv;
            *(float4*)&sB[lr * 68 + lc + 4 * q] = av;
        }
    }
    for (int idx = tid; idx < 4096; idx += 256) {
        int l = idx >> 6, p = idx & 63;
        sCI[p * 68 + l] = g_CI[k * 4096 + idx];
    }
    __syncthreads();

    const int td = (tid >> 4) << 2;
    const int tcl = (tid & 15) << 2;
    float wacc[4][4];
#pragma unroll
    for (int i = 0; i < 4; i++)
#pragma unroll
        for (int j = 0; j < 4; j++) wacc[i][j] = 0.f;
    for (int p = 0; p < 64; p++) {
        float la[4];
#pragma unroll
        for (int i = 0; i < 4; i++) la[i] = sB[(td + i) * 68 + p];
        float4 lcv = *(const float4*)&sCI[p * 68 + tcl];
        float lcj[4] = {lcv.x, lcv.y, lcv.z, lcv.w};
#pragma unroll
        for (int i = 0; i < 4; i++)
#pragma unroll
            for (int j = 0; j < 4; j++) wacc[i][j] += la[i] * lcj[j];
    }
#pragma unroll
    for (int i = 0; i < 4; i++) {
        float4 wv = make_float4(wacc[i][0], wacc[i][1], wacc[i][2], wacc[i][3]);
        *(float4*)&g_W[((size_t)k * Df + dt * 64 + td + i) * Lf + tcl] = wv;
    }
}

// ---------------------------------------------------------------------------
// prep3: build W B-fragments (bf16 hi/lo) in mma m16n8k16 col layout
// ---------------------------------------------------------------------------
__global__ __launch_bounds__(256) void prep3_kernel()
{
    int idx = blockIdx.x * 256 + threadIdx.x;   // 1048576 total
    int lane = idx & 31, lt = (idx >> 5) & 7, dc = (idx >> 8) & 31, k = idx >> 13;
    int g = lane >> 2, tg = lane & 3;
    int l = lt * 8 + g;
    const float* wp = g_W + ((size_t)k * Df + dc * 16 + tg * 2) * Lf + l;
    float w00 = wp[0];
    float w01 = wp[64];
    float w10 = wp[8 * 64];
    float w11 = wp[9 * 64];
    uint4 v;
    v.x = bfsplit(make_float2(w00, w01), v.z);
    v.y = bfsplit(make_float2(w10, w11), v.w);
    g_wf[idx] = v;
}

// ---------------------------------------------------------------------------
// q1: g_Q1[k][n] = sum_d x^2 iD - 2 x iDMU.  grid (64 ntile, 2 ktile)
// ---------------------------------------------------------------------------
__global__ __launch_bounds__(256) void q1_kernel(const float* __restrict__ x)
{
    __shared__ __align__(16) float sxt[64 * 20];
    __shared__ __align__(16) float sx2[64 * 20];
    __shared__ __align__(16) float sid[16 * 68];
    __shared__ __align__(16) float sim[16 * 68];

    const int n0 = blockIdx.x << 6;
    const int k0 = blockIdx.y << 6;
    const int tid = threadIdx.x;
    const int tn = (tid >> 4) << 2;
    const int tk = (tid & 15) << 2;
    const int xr = tid >> 2, xc = (tid & 3) << 2;
    const int ir = tid >> 4, ic = (tid & 15) << 2;

    ull acc2[4][2];
#pragma unroll
    for (int i = 0; i < 4; i++) { acc2[i][0] = 0ULL; acc2[i][1] = 0ULL; }

    for (int c = 0; c < 32; c++) {
        float4 v = *(const float4*)(x + (size_t)(n0 + xr) * Df + c * 16 + xc);
        *(float4*)&sxt[xr * 20 + xc] = v;
        float4 v2 = make_float4(v.x * v.x, v.y * v.y, v.z * v.z, v.w * v.w);
        *(float4*)&sx2[xr * 20 + xc] = v2;
        *(float4*)&sid[ir * 68 + ic] = *(const float4*)&g_iDT[(size_t)(c * 16 + ir) * Kc + k0 + ic];
        *(float4*)&sim[ir * 68 + ic] = *(const float4*)&g_m2iMT[(size_t)(c * 16 + ir) * Kc + k0 + ic];
        __syncthreads();
#pragma unroll
        for (int dd = 0; dd < 16; dd++) {
            ulonglong2 idp = *(const ulonglong2*)&sid[dd * 68 + tk];
            ulonglong2 imp = *(const ulonglong2*)&sim[dd * 68 + tk];
#pragma unroll
            for (int i = 0; i < 4; i++) {
                float xv = sxt[(tn + i) * 20 + dd];
                float x2 = sx2[(tn + i) * 20 + dd];
                ull xp = pk(xv), x2p = pk(x2);
                FMA2(acc2[i][0], x2p, idp.x);
                FMA2(acc2[i][1], x2p, idp.y);
                FMA2(acc2[i][0], xp, imp.x);
                FMA2(acc2[i][1], xp, imp.y);
            }
        }
        __syncthreads();
    }
#pragma unroll
    for (int i = 0; i < 4; i++)
#pragma unroll
        for (int j = 0; j < 2; j++) {
            float2 f = u2f(acc2[i][j]);
            g_Q1[(size_t)(k0 + tk + 2 * j) * Nn + n0 + tn + i] = f.x;
            g_Q1[(size_t)(k0 + tk + 2 * j + 1) * Nn + n0 + tn + i] = f.y;
        }
}

// ---------------------------------------------------------------------------
// main: bf16-split tensor-core GEMM (mma.sync m16n8k16) + q2 epilogue.
// grid (32 nblk, 128 k), 128 threads (4 warps). Warp w: rows [w*32, w*32+32),
// full l=64. 3-stage cp.async pipeline on precomputed fragments.
// Stage layout (uint4): [0..511] x frags (8 ntiles x {hi,lo} x 32 lanes),
//                       [512..767] W frags (8 ltiles x 32 lanes).
// ---------------------------------------------------------------------------
__global__ __launch_bounds__(128) void main_kernel()
{
    __shared__ __align__(16) uint4 sbuf[3][768];
    __shared__ float sNKW[64];

    const int tid = threadIdx.x;
    const int w = tid >> 5, lane = tid & 31;
    const int g = lane >> 2, tg = lane & 3;
    const int b = blockIdx.x, k = blockIdx.y;

    if (tid < 64) sNKW[tid] = g_nkw[k * Lf + tid];

    float acc[2][8][4];
#pragma unroll
    for (int mt = 0; mt < 2; mt++)
#pragma unroll
        for (int nt = 0; nt < 8; nt++)
#pragma unroll
            for (int j = 0; j < 4; j++) acc[mt][nt][j] = 0.f;

#define ISSUE(c, s) do { \
    const uint4* xs_ = g_xf + (size_t)(c) * 16384 + (size_t)b * 512; \
    uint32_t d0_ = smem_u32(&sbuf[s][0]); \
    CP16(d0_ + (uint32_t)(tid * 16),          xs_ + tid); \
    CP16(d0_ + (uint32_t)((tid + 128) * 16),  xs_ + tid + 128); \
    CP16(d0_ + (uint32_t)((tid + 256) * 16),  xs_ + tid + 256); \
    CP16(d0_ + (uint32_t)((tid + 384) * 16),  xs_ + tid + 384); \
    const uint4* ws_ = g_wf + ((size_t)k * 32 + (c)) * 256; \
    CP16(d0_ + (uint32_t)((512 + tid) * 16),  ws_ + tid); \
    CP16(d0_ + (uint32_t)((640 + tid) * 16),  ws_ + tid + 128); \
    asm volatile("cp.async.commit_group;" ::: "memory"); \
} while (0)

    ISSUE(0, 0);
    ISSUE(1, 1);

    int st = 0;
    for (int c = 0; c < 32; c++) {
        if (c < 31) asm volatile("cp.async.wait_group 1;" ::: "memory");
        else        asm volatile("cp.async.wait_group 0;" ::: "memory");
        __syncthreads();

        const uint4* sx = sbuf[st];
        uint4 Ah0 = sx[(4 * w + 0) * 32 + lane];
        uint4 Al0 = sx[(4 * w + 1) * 32 + lane];
        uint4 Ah1 = sx[(4 * w + 2) * 32 + lane];
        uint4 Al1 = sx[(4 * w + 3) * 32 + lane];
        const uint4* swp = sx + 512;
#pragma unroll
        for (int nt = 0; nt < 8; nt++) {
            uint4 B = swp[nt * 32 + lane];  // {bhi0, bhi1, blo0, blo1}
            MMA(acc[0][nt], Ah0, B.x, B.y);
            MMA(acc[0][nt], Ah0, B.z, B.w);
            MMA(acc[0][nt], Al0, B.x, B.y);
            MMA(acc[1][nt], Ah1, B.x, B.y);
            MMA(acc[1][nt], Ah1, B.z, B.w);
            MMA(acc[1][nt], Al1, B.x, B.y);
        }
        if (c + 2 < 32) {
            int s2 = st + 2; if (s2 >= 3) s2 -= 3;
            ISSUE(c + 2, s2);
        }
        st++; if (st == 3) st = 0;
    }
#undef ISSUE

    // epilogue: q2 = sum_l (t + nkw)^2 from accumulators
    float nk[16];
#pragma unroll
    for (int nt = 0; nt < 8; nt++) {
        nk[2 * nt]     = sNKW[nt * 8 + 2 * tg];
        nk[2 * nt + 1] = sNKW[nt * 8 + 2 * tg + 1];
    }
    const float coef = g_coef[k];
#pragma unroll
    for (int mt = 0; mt < 2; mt++) {
        float q20 = 0.f, q21 = 0.f;
#pragma unroll
        for (int nt = 0; nt < 8; nt++) {
            float t0 = acc[mt][nt][0] + nk[2 * nt];
            float t1 = acc[mt][nt][1] + nk[2 * nt + 1];
            float t2 = acc[mt][nt][2] + nk[2 * nt];
            float t3 = acc[mt][nt][3] + nk[2 * nt + 1];
            q20 += t0 * t0 + t1 * t1;
            q21 += t2 * t2 + t3 * t3;
        }
        q20 += __shfl_xor_sync(0xffffffffu, q20, 1);
        q20 += __shfl_xor_sync(0xffffffffu, q20, 2);
        q21 += __shfl_xor_sync(0xffffffffu, q21, 1);
        q21 += __shfl_xor_sync(0xffffffffu, q21, 2);
        if (tg == 0) {
            int r0 = w * 32 + mt * 16 + g;          // rows r0 and r0+8
            int n = b * 128 + r0;
            float pc0 = coef - 0.5f * (g_Q1[(size_t)k * Nn + n] - q20);
            float pc1 = coef - 0.5f * (g_Q1[(size_t)k * Nn + n + 8] - q21);
            g_PC[(size_t)k * Nn + n] = pc0;
            g_PC[(size_t)k * Nn + n + 8] = pc1;
        }
    }
}

// ---------------------------------------------------------------------------
// lse: 4 threads per n, logsumexp over k.  grid 64, block 256.
// ---------------------------------------------------------------------------
__global__ __launch_bounds__(256) void lse_kernel(float* __restrict__ out)
{
    const int tid = threadIdx.x;
    const int q = tid & 3;
    const int n = blockIdx.x * 64 + (tid >> 2);
    const float* pc = g_PC + n + (size_t)q * 32 * Nn;

    float v[32];
#pragma unroll
    for (int j = 0; j < 32; j++) v[j] = pc[(size_t)j * Nn];
    float mx = v[0];
#pragma unroll
    for (int j = 1; j < 32; j++) mx = fmaxf(mx, v[j]);
    mx = fmaxf(mx, __shfl_xor_sync(0xffffffffu, mx, 1));
    mx = fmaxf(mx, __shfl_xor_sync(0xffffffffu, mx, 2));
    float s = 0.f;
#pragma unroll
    for (int j = 0; j < 32; j++) s += expf(v[j] - mx);
    s += __shfl_xor_sync(0xffffffffu, s, 1);
    s += __shfl_xor_sync(0xffffffffu, s, 2);
    if (q == 0) out[n] = mx + logf(s);
}

extern "C" void kernel_launch(void* const* d_in, const int* in_sizes, int n_in,
                              void* d_out, int out_size)
{
    const float* x  = (const float*)d_in[0];
    const float* MU = (const float*)d_in[1];
    const float* A  = (const float*)d_in[2];
    const float* Dm = (const float*)d_in[3];
    const float* PI = (const float*)d_in[4];
    float* out = (float*)d_out;

    xcvt_kernel<<<1024, 256>>>(x);
    prep1_kernel<<<Kc, 256>>>(A, MU, Dm, PI);
    prep2_kernel<<<dim3(8, Kc), 256>>>(A);
    prep3_kernel<<<4096, 256>>>();
    q1_kernel<<<dim3(Nn / 64, Kc / 64), 256>>>(x);
    main_kernel<<<dim3(Nn / 128, Kc), 128>>>();
    lse_kernel<<<Nn / 64, 256>>>(out);
}

// round 7
// speedup vs baseline: 4.1215x; 1.4291x over previous
#include <cuda_runtime.h>
#include <cuda_fp16.h>
#include <stdint.h>
#include <math.h>

#define Kc 128
#define Df 512
#define Lf 64
#define Nn 4096

// ln(2*pi) * 512
#define CONST_TERM 940.9930580015849f

typedef unsigned long long ull;

// packed f32x2 helpers (sm_100+ PTX)
#define FMA2(acc, a, b) asm("fma.rn.f32x2 %0, %1, %2, %0;" : "+l"(acc) : "l"(a), "l"(b))
#define MUL2(d, a, b)   asm("mul.rn.f32x2 %0, %1, %2;" : "=l"(d) : "l"(a), "l"(b))

__device__ __forceinline__ ull pk(float v) {
    ull r; asm("mov.b64 %0, {%1, %1};" : "=l"(r) : "f"(v)); return r;
}
__device__ __forceinline__ float2 u2f(ull u) {
    float2 f; asm("mov.b64 {%0, %1}, %2;" : "=f"(f.x), "=f"(f.y) : "l"(u)); return f;
}
__device__ __forceinline__ uint32_t smem_u32(const void* p) {
    uint32_t a;
    asm("{ .reg .u64 t; cvta.to.shared.u64 t, %1; cvt.u32.u64 %0, t; }" : "=r"(a) : "l"(p));
    return a;
}
__device__ __forceinline__ uint32_t h2pack(float a, float b) {
    __half2 h = __floats2half2_rn(a, b);
    return *(uint32_t*)&h;
}

// mma.sync m16n8k16 fp16 (A row, B col, f32 accum)
#define MMA(d, a, b0, b1) \
    asm volatile("mma.sync.aligned.m16n8k16.row.col.f32.f16.f16.f32 " \
        "{%0,%1,%2,%3}, {%4,%5,%6,%7}, {%8,%9}, {%0,%1,%2,%3};" \
        : "+f"((d)[0]), "+f"((d)[1]), "+f"((d)[2]), "+f"((d)[3]) \
        : "r"((a).x), "r"((a).y), "r"((a).z), "r"((a).w), "r"(b0), "r"(b1))

#define CP16(dst_u32, src_ptr) \
    asm volatile("cp.async.ca.shared.global [%0], [%1], 16;" :: "r"(dst_u32), "l"(src_ptr) : "memory")

// ---------------- device scratch ----------------
__device__ __align__(16) float g_iD[Kc * Df];
__device__ __align__(16) float g_iDT[Df * Kc];             // [d][k]
__device__ __align__(16) float g_m2iMT[Df * Kc];           // [d][k] = -2*iD*MU
__device__ __align__(16) float g_CI[Kc * Lf * Lf];         // Cinv[i][j]
__device__ __align__(16) float g_nkw[Kc * Lf];             // -(W^T MU)
__device__ __align__(16) float g_coef[Kc];
__device__ __align__(16) float g_Q1[(size_t)Kc * Nn];      // q1 = x^2 iD - 2 x iDMU
__device__ __align__(16) float g_PC[(size_t)Kc * Nn];      // per-comp log dens [k][n]
// x A-frags (fp16): [dc 32][ntile 256][lane 32] uint4        (4 MB)
__device__ __align__(16) uint4 g_xf[32 * 256 * 32];
// W B-frags (fp16): [k 128][dc 32][lt 8][lane 32] uint2      (8 MB)
__device__ __align__(16) uint2 g_wf[(size_t)Kc * 32 * 8 * 32];

// ---------------------------------------------------------------------------
// xcvt: build x A-fragments (fp16) in mma m16n8k16 layout
// ---------------------------------------------------------------------------
__global__ __launch_bounds__(256) void xcvt_kernel(const float* __restrict__ x)
{
    int idx = blockIdx.x * 256 + threadIdx.x;       // 262144 total
    int lane = idx & 31, nt = (idx >> 5) & 255, dc = idx >> 13;
    int g = lane >> 2, tg = lane & 3;
    const float* xr0 = x + (size_t)(nt * 16 + g) * Df + dc * 16 + tg * 2;
    float2 e00 = *(const float2*)xr0;               // row g,   k 2tg..2tg+1
    float2 e10 = *(const float2*)(xr0 + 8 * Df);    // row g+8
    float2 e01 = *(const float2*)(xr0 + 8);         // row g,   k +8
    float2 e11 = *(const float2*)(xr0 + 8 * Df + 8);
    uint4 v;
    v.x = h2pack(e00.x, e00.y);
    v.y = h2pack(e10.x, e10.y);
    v.z = h2pack(e01.x, e01.y);
    v.w = h2pack(e11.x, e11.y);
    g_xf[(size_t)(dc * 256 + nt) * 32 + lane] = v;
}

// ---------------------------------------------------------------------------
// prep1: per k: iD, iDMU (+transposed), Lmat = I + A^T diag(iD) A (f32x2,
// register-prefetched), Cholesky, Cinv, nkw, coef.
// ---------------------------------------------------------------------------
__global__ __launch_bounds__(256) void prep1_kernel(const float* __restrict__ A,
                                                    const float* __restrict__ MU,
                                                    const float* __restrict__ Dm,
                                                    const float* __restrict__ PI)
{
    __shared__ float sLM[64 * 65];
    __shared__ float sCIT[64 * 68];   // sCIT[j*68+i] = Cinv[i][j]
    __shared__ float siD[512];
    __shared__ float siMU[512];
    __shared__ float sA[16 * 64];
    __shared__ float scinv[64];
    __shared__ float sv[64];
    __shared__ float sred[256];
    __shared__ float s_c1, s_slog;

    const int k = blockIdx.x;
    const int tid = threadIdx.x;
#define LM(i, j) sLM[(i) * 65 + (j)]

    float c1p = 0.f, slp = 0.f;
    for (int d = tid; d < Df; d += 256) {
        float dv = Dm[k * Df + d];
        float id = 1.f / (dv * dv);
        siD[d] = id;
        g_iD[k * Df + d] = id;
        g_iDT[d * Kc + k] = id;
        float mu = MU[k * Df + d];
        float im = id * mu;
        siMU[d] = im;
        g_m2iMT[d * Kc + k] = -2.f * im;
        c1p += im * mu;
        slp += logf(id);
    }
    sred[tid] = c1p; __syncthreads();
    for (int s = 128; s > 0; s >>= 1) { if (tid < s) sred[tid] += sred[tid + s]; __syncthreads(); }
    if (tid == 0) s_c1 = sred[0];
    __syncthreads();
    sred[tid] = slp; __syncthreads();
    for (int s = 128; s > 0; s >>= 1) { if (tid < s) sred[tid] += sred[tid + s]; __syncthreads(); }
    if (tid == 0) s_slog = sred[0];
    __syncthreads();

    const int tl = (tid >> 4) << 2;
    const int tm = (tid & 15) << 2;
    ull lacc2[4][2];
#pragma unroll
    for (int i = 0; i < 4; i++) { lacc2[i][0] = 0ULL; lacc2[i][1] = 0ULL; }
    float vacc = 0.f;

    const float* Ak = A + (size_t)k * Df * Lf;
    float4 apre = *(const float4*)(Ak + tid * 4);
    for (int d0 = 0; d0 < Df; d0 += 16) {
        *(float4*)&sA[tid * 4] = apre;
        __syncthreads();
        if (d0 + 16 < Df)
            apre = *(const float4*)(Ak + (size_t)(d0 + 16) * 64 + tid * 4);
#pragma unroll
        for (int dd = 0; dd < 16; dd++) {
            ull idp = pk(siD[d0 + dd]);
            float4 lav = *(const float4*)&sA[dd * 64 + tl];
            ulonglong2 bb = *(const ulonglong2*)&sA[dd * 64 + tm];
            ull lb0, lb1;
            MUL2(lb0, bb.x, idp);
            MUL2(lb1, bb.y, idp);
            float la[4] = {lav.x, lav.y, lav.z, lav.w};
#pragma unroll
            for (int i = 0; i < 4; i++) {
                ull ai = pk(la[i]);
                FMA2(lacc2[i][0], ai, lb0);
                FMA2(lacc2[i][1], ai, lb1);
            }
        }
        if (tid < 64) {
#pragma unroll
            for (int dd = 0; dd < 16; dd++)
                vacc += siMU[d0 + dd] * sA[dd * 64 + tid];
        }
        __syncthreads();
    }
#pragma unroll
    for (int i = 0; i < 4; i++) {
        float2 f0 = u2f(lacc2[i][0]);
        float2 f1 = u2f(lacc2[i][1]);
        float w[4] = {f0.x, f0.y, f1.x, f1.y};
#pragma unroll
        for (int j = 0; j < 4; j++)
            LM(tl + i, tm + j) = w[j] + ((tl + i) == (tm + j) ? 1.f : 0.f);
    }
    if (tid < 64) sv[tid] = vacc;
    __syncthreads();

    // Cholesky
    for (int j = 0; j < 64; j++) {
        if (tid >= j && tid < 64) {
            float s0 = LM(tid, j), s1 = 0.f;
            int p = 0;
            for (; p + 1 < j; p += 2) {
                s0 -= LM(tid, p) * LM(j, p);
                s1 -= LM(tid, p + 1) * LM(j, p + 1);
            }
            if (p < j) s0 -= LM(tid, p) * LM(j, p);
            LM(tid, j) = s0 + s1;
        }
        __syncthreads();
        if (tid == 0) {
            float dv = sqrtf(LM(j, j));
            LM(j, j) = dv;
            scinv[j] = 1.f / dv;
        }
        __syncthreads();
        if (tid > j && tid < 64) LM(tid, j) *= scinv[j];
        __syncthreads();
    }
    if (tid == 0) {
        float ld = 0.f;
        for (int j = 0; j < 64; j++) ld += logf(LM(j, j));
        ld *= 2.f;
        g_coef[k] = PI[k] - 0.5f * (CONST_TERM + (ld - s_slog) + s_c1);
    }

    // triangular inverse (thread j owns column j), dual accumulators
    for (int idx = tid; idx < 64 * 68; idx += 256) sCIT[idx] = 0.f;
    __syncthreads();
    if (tid < 64) {
        const int j = tid;
        for (int i = j; i < 64; i++) {
            float s0 = (i == j) ? 1.f : 0.f, s1 = 0.f;
            int p = j;
            for (; p + 1 < i; p += 2) {
                s0 -= LM(i, p) * sCIT[j * 68 + p];
                s1 -= LM(i, p + 1) * sCIT[j * 68 + p + 1];
            }
            if (p < i) s0 -= LM(i, p) * sCIT[j * 68 + p];
            sCIT[j * 68 + i] = (s0 + s1) * scinv[i];
        }
    }
    __syncthreads();

    if (tid < 64) {
        float s = 0.f;
        for (int p = 0; p < 64; p++) s += sCIT[p * 68 + tid] * sv[p];
        g_nkw[k * Lf + tid] = -s;
    }
    for (int idx = tid; idx < 4096; idx += 256) {
        int i = idx >> 6, j = idx & 63;
        g_CI[k * 4096 + idx] = (j <= i) ? sCIT[j * 68 + i] : 0.f;
    }
#undef LM
}

// ---------------------------------------------------------------------------
// prep2: W chunk GEMM (f32) fused with fp16 B-fragment emission; grid (8,128)
// ---------------------------------------------------------------------------
__global__ __launch_bounds__(256) void prep2_kernel(const float* __restrict__ A)
{
    __shared__ float sB[64 * 68];    // (iD*A)[d][p]
    __shared__ float sCI[64 * 68];   // sCI[p*68 + l] = Cinv[l][p]
    __shared__ float sW[64 * 65];    // W[d][l]

    const int k = blockIdx.y;
    const int dt = blockIdx.x;
    const int tid = threadIdx.x;

    {
        int lr = tid >> 2;
        int lc = (tid & 3) << 4;
        float idv = g_iD[k * Df + dt * 64 + lr];
        const float* ar = A + ((size_t)k * Df + dt * 64 + lr) * Lf + lc;
#pragma unroll
        for (int q = 0; q < 4; q++) {
            float4 av = *(const float4*)(ar + 4 * q);
            av.x *= idv; av.y *= idv; av.z *= idv; av.w *= idv;
            *(float4*)&sB[lr * 68 + lc + 4 * q] = av;
        }
    }
    for (int idx = tid; idx < 4096; idx += 256) {
        int l = idx >> 6, p = idx & 63;
        sCI[p * 68 + l] = g_CI[k * 4096 + idx];
    }
    __syncthreads();

    const int td = (tid >> 4) << 2;
    const int tcl = (tid & 15) << 2;
    float wacc[4][4];
#pragma unroll
    for (int i = 0; i < 4; i++)
#pragma unroll
        for (int j = 0; j < 4; j++) wacc[i][j] = 0.f;
    for (int p = 0; p < 64; p++) {
        float la[4];
#pragma unroll
        for (int i = 0; i < 4; i++) la[i] = sB[(td + i) * 68 + p];
        float4 lcv = *(const float4*)&sCI[p * 68 + tcl];
        float lcj[4] = {lcv.x, lcv.y, lcv.z, lcv.w};
#pragma unroll
        for (int i = 0; i < 4; i++)
#pragma unroll
            for (int j = 0; j < 4; j++) wacc[i][j] += la[i] * lcj[j];
    }
#pragma unroll
    for (int i = 0; i < 4; i++)
#pragma unroll
        for (int j = 0; j < 4; j++)
            sW[(td + i) * 65 + tcl + j] = wacc[i][j];
    __syncthreads();

    // emit fp16 B-frags: 4 chunks x [lt 8][lane 32] uint2
    const int lane = tid & 31, lt = (tid >> 5) & 7;
    const int g = lane >> 2, tg = lane & 3;
    const int l = lt * 8 + g;
#pragma unroll
    for (int ch = 0; ch < 4; ch++) {
        int d0 = ch * 16 + 2 * tg;
        uint2 v;
        v.x = h2pack(sW[d0 * 65 + l], sW[(d0 + 1) * 65 + l]);
        v.y = h2pack(sW[(d0 + 8) * 65 + l], sW[(d0 + 9) * 65 + l]);
        g_wf[(((size_t)k * 32 + dt * 4 + ch) * 8 + lt) * 32 + lane] = v;
    }
}

// ---------------------------------------------------------------------------
// q1: g_Q1[k][n] = sum_d x^2 iD - 2 x iDMU.  grid (64 ntile, 2 ktile)
// ---------------------------------------------------------------------------
__global__ __launch_bounds__(256) void q1_kernel(const float* __restrict__ x)
{
    __shared__ __align__(16) float sxt[64 * 20];
    __shared__ __align__(16) float sx2[64 * 20];
    __shared__ __align__(16) float sid[16 * 68];
    __shared__ __align__(16) float sim[16 * 68];

    const int n0 = blockIdx.x << 6;
    const int k0 = blockIdx.y << 6;
    const int tid = threadIdx.x;
    const int tn = (tid >> 4) << 2;
    const int tk = (tid & 15) << 2;
    const int xr = tid >> 2, xc = (tid & 3) << 2;
    const int ir = tid >> 4, ic = (tid & 15) << 2;

    ull acc2[4][2];
#pragma unroll
    for (int i = 0; i < 4; i++) { acc2[i][0] = 0ULL; acc2[i][1] = 0ULL; }

    for (int c = 0; c < 32; c++) {
        float4 v = *(const float4*)(x + (size_t)(n0 + xr) * Df + c * 16 + xc);
        *(float4*)&sxt[xr * 20 + xc] = v;
        float4 v2 = make_float4(v.x * v.x, v.y * v.y, v.z * v.z, v.w * v.w);
        *(float4*)&sx2[xr * 20 + xc] = v2;
        *(float4*)&sid[ir * 68 + ic] = *(const float4*)&g_iDT[(size_t)(c * 16 + ir) * Kc + k0 + ic];
        *(float4*)&sim[ir * 68 + ic] = *(const float4*)&g_m2iMT[(size_t)(c * 16 + ir) * Kc + k0 + ic];
        __syncthreads();
#pragma unroll
        for (int dd = 0; dd < 16; dd++) {
            ulonglong2 idp = *(const ulonglong2*)&sid[dd * 68 + tk];
            ulonglong2 imp = *(const ulonglong2*)&sim[dd * 68 + tk];
#pragma unroll
            for (int i = 0; i < 4; i++) {
                float xv = sxt[(tn + i) * 20 + dd];
                float x2 = sx2[(tn + i) * 20 + dd];
                ull xp = pk(xv), x2p = pk(x2);
                FMA2(acc2[i][0], x2p, idp.x);
                FMA2(acc2[i][1], x2p, idp.y);
                FMA2(acc2[i][0], xp, imp.x);
                FMA2(acc2[i][1], xp, imp.y);
            }
        }
        __syncthreads();
    }
#pragma unroll
    for (int i = 0; i < 4; i++)
#pragma unroll
        for (int j = 0; j < 2; j++) {
            float2 f = u2f(acc2[i][j]);
            g_Q1[(size_t)(k0 + tk + 2 * j) * Nn + n0 + tn + i] = f.x;
            g_Q1[(size_t)(k0 + tk + 2 * j + 1) * Nn + n0 + tn + i] = f.y;
        }
}

// ---------------------------------------------------------------------------
// main: fp16 single-pass tensor GEMM + q2 epilogue.
// grid (32 nblk, 64 kpair), 256 threads (8 warps).
// Warps 0-3 -> k = 2*kp, warps 4-7 -> k = 2*kp+1; warp (w&3) covers rows
// (w&3)*32..+31 (2 mtiles). 3-stage cp.async pipeline on fragments.
// ---------------------------------------------------------------------------
__global__ __launch_bounds__(256) void main_kernel()
{
    __shared__ __align__(16) uint4 sA[3][256];          // 8 ntiles x 32 lanes
    __shared__ __align__(16) uint2 sB[3][2][256];       // [kk][lt*32+lane]
    __shared__ float sNKW[2][64];

    const int tid = threadIdx.x;
    const int w = tid >> 5, lane = tid & 31;
    const int g = lane >> 2, tg = lane & 3;
    const int b = blockIdx.x, kp = blockIdx.y;
    const int kk = w >> 2;
    const int k = kp * 2 + kk;
    const int mw = w & 3;

    if (tid < 128) sNKW[tid >> 6][tid & 63] = g_nkw[(kp * 2 + (tid >> 6)) * Lf + (tid & 63)];

    float acc[2][8][4];
#pragma unroll
    for (int mt = 0; mt < 2; mt++)
#pragma unroll
        for (int lt = 0; lt < 8; lt++)
#pragma unroll
            for (int j = 0; j < 4; j++) acc[mt][lt][j] = 0.f;

    const int kb = tid >> 7;            // which k this thread loads B for
    const int bi = tid & 127;

#define ISSUE(c, s) do { \
    uint32_t da_ = smem_u32(&sA[s][0]); \
    CP16(da_ + (uint32_t)(tid * 16), g_xf + (size_t)((c) * 256 + b * 8) * 32 + tid); \
    const uint4* ws_ = (const uint4*)(g_wf + ((size_t)(kp * 2 + kb) * 32 + (c)) * 256); \
    uint32_t db_ = smem_u32(&sB[s][kb][0]); \
    CP16(db_ + (uint32_t)(bi * 16), ws_ + bi); \
    asm volatile("cp.async.commit_group;" ::: "memory"); \
} while (0)

    ISSUE(0, 0);
    ISSUE(1, 1);

    int st = 0;
    for (int c = 0; c < 32; c++) {
        if (c < 31) asm volatile("cp.async.wait_group 1;" ::: "memory");
        else        asm volatile("cp.async.wait_group 0;" ::: "memory");
        __syncthreads();

        uint4 A0 = sA[st][(mw * 2) * 32 + lane];
        uint4 A1 = sA[st][(mw * 2 + 1) * 32 + lane];
        const uint2* bp = &sB[st][kk][0];
#pragma unroll
        for (int lt = 0; lt < 8; lt++) {
            uint2 B = bp[lt * 32 + lane];
            MMA(acc[0][lt], A0, B.x, B.y);
            MMA(acc[1][lt], A1, B.x, B.y);
        }
        if (c + 2 < 32) {
            int s2 = st + 2; if (s2 >= 3) s2 -= 3;
            ISSUE(c + 2, s2);
        }
        st++; if (st == 3) st = 0;
    }
#undef ISSUE

    // epilogue: q2 = sum_l (t + nkw)^2
    float nk[16];
#pragma unroll
    for (int lt = 0; lt < 8; lt++) {
        nk[2 * lt]     = sNKW[kk][lt * 8 + 2 * tg];
        nk[2 * lt + 1] = sNKW[kk][lt * 8 + 2 * tg + 1];
    }
    const float coef = g_coef[k];
#pragma unroll
    for (int mt = 0; mt < 2; mt++) {
        float q20 = 0.f, q21 = 0.f;
#pragma unroll
        for (int lt = 0; lt < 8; lt++) {
            float t0 = acc[mt][lt][0] + nk[2 * lt];
            float t1 = acc[mt][lt][1] + nk[2 * lt + 1];
            float t2 = acc[mt][lt][2] + nk[2 * lt];
            float t3 = acc[mt][lt][3] + nk[2 * lt + 1];
            q20 += t0 * t0 + t1 * t1;
            q21 += t2 * t2 + t3 * t3;
        }
        q20 += __shfl_xor_sync(0xffffffffu, q20, 1);
        q20 += __shfl_xor_sync(0xffffffffu, q20, 2);
        q21 += __shfl_xor_sync(0xffffffffu, q21, 1);
        q21 += __shfl_xor_sync(0xffffffffu, q21, 2);
        if (tg == 0) {
            int n = b * 128 + mw * 32 + mt * 16 + g;    // rows n and n+8
            float pc0 = coef - 0.5f * (g_Q1[(size_t)k * Nn + n] - q20);
            float pc1 = coef - 0.5f * (g_Q1[(size_t)k * Nn + n + 8] - q21);
            g_PC[(size_t)k * Nn + n] = pc0;
            g_PC[(size_t)k * Nn + n + 8] = pc1;
        }
    }
}

// ---------------------------------------------------------------------------
// lse: 4 threads per n, logsumexp over k.  grid 64, block 256.
// ---------------------------------------------------------------------------
__global__ __launch_bounds__(256) void lse_kernel(float* __restrict__ out)
{
    const int tid = threadIdx.x;
    const int q = tid & 3;
    const int n = blockIdx.x * 64 + (tid >> 2);
    const float* pc = g_PC + n + (size_t)q * 32 * Nn;

    float v[32];
#pragma unroll
    for (int j = 0; j < 32; j++) v[j] = pc[(size_t)j * Nn];
    float mx = v[0];
#pragma unroll
    for (int j = 1; j < 32; j++) mx = fmaxf(mx, v[j]);
    mx = fmaxf(mx, __shfl_xor_sync(0xffffffffu, mx, 1));
    mx = fmaxf(mx, __shfl_xor_sync(0xffffffffu, mx, 2));
    float s = 0.f;
#pragma unroll
    for (int j = 0; j < 32; j++) s += expf(v[j] - mx);
    s += __shfl_xor_sync(0xffffffffu, s, 1);
    s += __shfl_xor_sync(0xffffffffu, s, 2);
    if (q == 0) out[n] = mx + logf(s);
}

extern "C" void kernel_launch(void* const* d_in, const int* in_sizes, int n_in,
                              void* d_out, int out_size)
{
    const float* x  = (const float*)d_in[0];
    const float* MU = (const float*)d_in[1];
    const float* A  = (const float*)d_in[2];
    const float* Dm = (const float*)d_in[3];
    const float* PI = (const float*)d_in[4];
    float* out = (float*)d_out;

    xcvt_kernel<<<1024, 256>>>(x);
    prep1_kernel<<<Kc, 256>>>(A, MU, Dm, PI);
    prep2_kernel<<<dim3(8, Kc), 256>>>(A);
    q1_kernel<<<dim3(Nn / 64, Kc / 64), 256>>>(x);
    main_kernel<<<dim3(Nn / 128, Kc / 2), 256>>>();
    lse_kernel<<<Nn / 64, 256>>>(out);
}